// round 16
// baseline (speedup 1.0000x reference)
#include <cuda_runtime.h>
#include <cuda_fp16.h>

// Problem constants
#define BATCH    8
#define S_BYTES  8192
#define NUM_EMB  384
#define BYTE_DIM 128
#define EMB_DIM  1024
#define NUM_TOK  2048
#define SCALE_F  11.313708498984761f  // sqrt(128)

#define GEMM_BLOCKS 384                       // 12 x 32 tiles of 32x32
#define POOL_BLOCKS (NUM_TOK / 8 * BATCH)     // 2048
#define BM 32
#define BN 32
#define SPITCH 33

// proj = SCALE * emb @ W^T, stored fp16 (768 KB, L2-resident)
__device__ __half g_proj_h[NUM_EMB * EMB_DIM];
// Producer->consumer flag + self-reset counter (reset each launch by the
// last pool block AFTER all blocks have passed their wait -> replay-safe).
__device__ int g_ready = 0;
__device__ int g_fin   = 0;

// ---------------------------------------------------------------------------
// Warp-cooperative lower_bound over a sorted row of S_BYTES ints.
// (Validated rounds 13-15.)
// ---------------------------------------------------------------------------
__device__ __forceinline__ int warp_lower_bound(const int* __restrict__ row,
                                                int v, int lane) {
    bool pr = row[lane << 8] < v;
    int c1 = __popc(__ballot_sync(0xffffffffu, pr));
    int base = c1 << 8;

    int p2 = base - 255 + (lane << 3);
    pr = (p2 < 0) || (row[p2] < v);
    int c2 = __popc(__ballot_sync(0xffffffffu, pr));
    int L = base + (c2 << 3) - 262;

    int p3 = L + lane;
    pr = (p3 < 0) || (p3 < S_BYTES && row[p3] < v);
    int c3 = __popc(__ballot_sync(0xffffffffu, pr) & 0xff);
    return L + c3;
}

// ---------------------------------------------------------------------------
// Fused kernel.
// Blocks [0, 384): tiny GEMM proj = SCALE*emb@W^T (32x32 tile, fp16 store),
//   then release g_ready.
// Blocks [384, 2432): pool. Bounds search FIRST (doesn't need proj, overlaps
//   with the GEMM), then acquire-wait on g_ready, then gather + store.
// Wave-1 = 4 CTAs/SM x 148 = 592 blocks >= 384 GEMM blocks (lowest ids),
// so producers always run ahead of spinners: no deadlock.
// ---------------------------------------------------------------------------
__global__ __launch_bounds__(256) void fused_kernel(const float* __restrict__ emb,
                                                    const float* __restrict__ W,
                                                    const int* __restrict__ x,
                                                    const int* __restrict__ bg,
                                                    float* __restrict__ out) {
    const int tid = threadIdx.x;

    if (blockIdx.x < GEMM_BLOCKS) {
        // ---------------- GEMM path ----------------
        __shared__ float As[BYTE_DIM][SPITCH];  // [k][m]
        __shared__ float Ws[BYTE_DIM][SPITCH];  // [k][n]

        const int bn = blockIdx.x & 31;   // 0..31
        const int bm = blockIdx.x >> 5;   // 0..11
        const int tx = tid & 15;
        const int ty = tid >> 4;
        const int m0 = ty * 2;
        const int n0 = tx * 2;

        const float* __restrict__ A  = emb + (size_t)(bm * BM) * BYTE_DIM;
        const float* __restrict__ Wt = W   + (size_t)(bn * BN) * BYTE_DIM;

        #pragma unroll
        for (int i = 0; i < 16; ++i) {
            int f = tid + i * 256;
            int k = f & 127;
            int r = f >> 7;
            As[k][r] = A [(size_t)r * BYTE_DIM + k];
            Ws[k][r] = Wt[(size_t)r * BYTE_DIM + k];
        }
        __syncthreads();

        float acc[2][2] = {};
        #pragma unroll 8
        for (int k = 0; k < BYTE_DIM; ++k) {
            float a0 = As[k][m0], a1 = As[k][m0 + 1];
            float w0 = Ws[k][n0], w1 = Ws[k][n0 + 1];
            acc[0][0] = fmaf(a0, w0, acc[0][0]);
            acc[0][1] = fmaf(a0, w1, acc[0][1]);
            acc[1][0] = fmaf(a1, w0, acc[1][0]);
            acc[1][1] = fmaf(a1, w1, acc[1][1]);
        }

        #pragma unroll
        for (int i = 0; i < 2; ++i) {
            __half2 h = __floats2half2_rn(acc[i][0] * SCALE_F, acc[i][1] * SCALE_F);
            *reinterpret_cast<__half2*>(
                g_proj_h + (size_t)(bm * BM + m0 + i) * EMB_DIM + bn * BN + n0) = h;
        }

        // Release: make this block's proj stores visible, then signal.
        __threadfence();
        __syncthreads();
        if (tid == 0) atomicAdd(&g_ready, 1);
        return;
    }

    // ---------------- Pool path ----------------
    const int blk  = blockIdx.x - GEMM_BLOCKS;   // 0..2047
    const int bx   = blk & 255;                  // token-group
    const int b    = blk >> 8;                   // batch
    const int wid  = tid >> 5;
    const int lane = tid & 31;
    const int t    = bx * 8 + wid;

    // Bounds search first — independent of proj, overlaps with the GEMM.
    const int* __restrict__ row = bg + (size_t)b * S_BYTES;
    const int s0 = warp_lower_bound(row, t, lane);

    int s1 = s0;
    for (;;) {
        int p = s1 + lane;
        bool pr = (p < S_BYTES) && (row[p] < t + 1);
        unsigned m = __ballot_sync(0xffffffffu, pr);
        s1 += __popc(m);
        if (m != 0xffffffffu) break;
    }
    const int cnt = s1 - s0;

    // Acquire-wait for the GEMM to finish.
    if (tid == 0) {
        while (atomicAdd(&g_ready, 0) < GEMM_BLOCKS) __nanosleep(64);
    }
    __syncthreads();
    __threadfence();  // order the gather loads after the observed flag

    const int* __restrict__ xr = x + (size_t)b * S_BYTES;
    const uint2* __restrict__ p = reinterpret_cast<const uint2*>(g_proj_h);  // 256/row

    float4 acc[8];
    #pragma unroll
    for (int j = 0; j < 8; ++j) acc[j] = make_float4(0.f, 0.f, 0.f, 0.f);

    for (int s = s0; s < s1; ++s) {
        const int e = xr[s];  // warp-broadcast load, L1-hit
        const uint2* __restrict__ pr = p + (size_t)e * (EMB_DIM / 4);
        #pragma unroll
        for (int j = 0; j < 8; ++j) {
            uint2 u = pr[lane + 32 * j];  // coalesced 256B wavefront, L2-hit
            __half2 h0 = *reinterpret_cast<__half2*>(&u.x);
            __half2 h1 = *reinterpret_cast<__half2*>(&u.y);
            float2 f0 = __half22float2(h0);
            float2 f1 = __half22float2(h1);
            acc[j].x += f0.x; acc[j].y += f0.y;
            acc[j].z += f1.x; acc[j].w += f1.y;
        }
    }

    const float inv = 1.0f / (float)(cnt > 0 ? cnt : 1);

    float4* __restrict__ o =
        reinterpret_cast<float4*>(out) + (((size_t)b * NUM_TOK) + t) * (EMB_DIM / 4);
    #pragma unroll
    for (int j = 0; j < 8; ++j) {
        float4 v = make_float4(acc[j].x * inv, acc[j].y * inv,
                               acc[j].z * inv, acc[j].w * inv);
        __stcs(&o[lane + 32 * j], v);  // contiguous STG.128.CS
    }

    // Self-reset for the next (graph-replayed) launch. The resetter is the
    // LAST pool block to finish -> every block has already passed its wait.
    __syncthreads();
    if (tid == 0) {
        int v = atomicAdd(&g_fin, 1);
        if (v == POOL_BLOCKS - 1) {
            g_ready = 0;
            g_fin   = 0;
            __threadfence();
        }
    }
}

// ---------------------------------------------------------------------------
// Launch
// ---------------------------------------------------------------------------
extern "C" void kernel_launch(void* const* d_in, const int* in_sizes, int n_in,
                              void* d_out, int out_size) {
    const int*   x    = (const int*)  d_in[0];  // [B, S_BYTES] int32
    const int*   bg   = (const int*)  d_in[1];  // [B, S_BYTES] int32 (sorted per row)
    const float* emb  = (const float*)d_in[2];  // [NUM_EMB, BYTE_DIM] fp32
    const float* wout = (const float*)d_in[3];  // [EMB_DIM, BYTE_DIM] fp32
    float* out = (float*)d_out;                 // [B, NUM_TOK, EMB_DIM] fp32

    (void)in_sizes; (void)n_in; (void)out_size;

    fused_kernel<<<GEMM_BLOCKS + POOL_BLOCKS, 256>>>(emb, wout, x, bg, out);
}

// round 17
// speedup vs baseline: 1.2739x; 1.2739x over previous
#include <cuda_runtime.h>
#include <cuda_fp16.h>

// Problem constants
#define BATCH    8
#define S_BYTES  8192
#define NUM_EMB  384
#define BYTE_DIM 128
#define EMB_DIM  1024
#define NUM_TOK  2048
#define SCALE_F  11.313708498984761f  // sqrt(128)

// proj = SCALE * emb @ W^T, stored fp16: [NUM_EMB, EMB_DIM] (768 KB, L2-resident)
__device__ __half g_proj_h[NUM_EMB * EMB_DIM];

// ---------------------------------------------------------------------------
// Kernel 1: tiny GEMM  proj[e][n] = SCALE * sum_k emb[e][k] * W[n][k]
// (unchanged round-15 version: 32x32 tiles, 384 blocks, fp16 store)
// ---------------------------------------------------------------------------
#define BM 32
#define BN 32
#define SPITCH 33

__global__ __launch_bounds__(256) void proj_gemm_kernel(const float* __restrict__ emb,
                                                        const float* __restrict__ W) {
    __shared__ float As[BYTE_DIM][SPITCH];  // [k][m]
    __shared__ float Ws[BYTE_DIM][SPITCH];  // [k][n]

    const int tid = threadIdx.x;
    const int bn = blockIdx.x & 31;
    const int bm = blockIdx.x >> 5;
    const int tx = tid & 15;
    const int ty = tid >> 4;
    const int m0 = ty * 2;
    const int n0 = tx * 2;

    const float* __restrict__ A  = emb + (size_t)(bm * BM) * BYTE_DIM;
    const float* __restrict__ Wt = W   + (size_t)(bn * BN) * BYTE_DIM;

    #pragma unroll
    for (int i = 0; i < 16; ++i) {
        int f = tid + i * 256;
        int k = f & 127;
        int r = f >> 7;
        As[k][r] = A [(size_t)r * BYTE_DIM + k];
        Ws[k][r] = Wt[(size_t)r * BYTE_DIM + k];
    }
    __syncthreads();

    float acc[2][2] = {};
    #pragma unroll 8
    for (int k = 0; k < BYTE_DIM; ++k) {
        float a0 = As[k][m0], a1 = As[k][m0 + 1];
        float w0 = Ws[k][n0], w1 = Ws[k][n0 + 1];
        acc[0][0] = fmaf(a0, w0, acc[0][0]);
        acc[0][1] = fmaf(a0, w1, acc[0][1]);
        acc[1][0] = fmaf(a1, w0, acc[1][0]);
        acc[1][1] = fmaf(a1, w1, acc[1][1]);
    }

    #pragma unroll
    for (int i = 0; i < 2; ++i) {
        __half2 h = __floats2half2_rn(acc[i][0] * SCALE_F, acc[i][1] * SCALE_F);
        *reinterpret_cast<__half2*>(
            g_proj_h + (size_t)(bm * BM + m0 + i) * EMB_DIM + bn * BN + n0) = h;
    }
}

// ---------------------------------------------------------------------------
// Warp-cooperative lower_bound (validated rounds 13-15).
// ---------------------------------------------------------------------------
__device__ __forceinline__ int warp_lower_bound(const int* __restrict__ row,
                                                int v, int lane) {
    bool pr = row[lane << 8] < v;
    int c1 = __popc(__ballot_sync(0xffffffffu, pr));
    int base = c1 << 8;

    int p2 = base - 255 + (lane << 3);
    pr = (p2 < 0) || (row[p2] < v);
    int c2 = __popc(__ballot_sync(0xffffffffu, pr));
    int L = base + (c2 << 3) - 262;

    int p3 = L + lane;
    pr = (p3 < 0) || (p3 < S_BYTES && row[p3] < v);
    int c3 = __popc(__ballot_sync(0xffffffffu, pr) & 0xff);
    return L + c3;
}

// Forward scan: first index >= start with row[idx] >= v (sorted row).
__device__ __forceinline__ int warp_scan_bound(const int* __restrict__ row,
                                               int v, int start, int lane) {
    int s = start;
    for (;;) {
        int p = s + lane;
        bool pr = (p < S_BYTES) && (row[p] < v);
        unsigned m = __ballot_sync(0xffffffffu, pr);
        s += __popc(m);
        if (m != 0xffffffffu) break;
    }
    return s;
}

// ---------------------------------------------------------------------------
// Kernel 2: ragged mean over fp16 proj rows. TWO adjacent tokens per warp:
// one 3-round search resolves s0(t0); two forward scans give the t0/t1
// boundary and t1's end (adjacent segments share a boundary). fp16 (HADD2)
// accumulation — 24 issue-slots per gathered byte vs 72 for the cvt+FADD
// version (numerics validated round 10). Gather/store patterns identical to
// the round-15 champion (coalesced uint2 loads, contiguous STG.128.CS).
// grid = (NUM_TOK/16, BATCH) = 1024 blocks, 256 threads (8 warps x 2 tokens).
// ---------------------------------------------------------------------------
__global__ __launch_bounds__(256) void pool_kernel(const int* __restrict__ x,
                                                   const int* __restrict__ bg,
                                                   float* __restrict__ out) {
    const int b    = blockIdx.y;
    const int wid  = threadIdx.x >> 5;
    const int lane = threadIdx.x & 31;
    const int t0   = blockIdx.x * 16 + wid * 2;

    const int* __restrict__ row = bg + (size_t)b * S_BYTES;
    const int s0   = warp_lower_bound(row, t0, lane);
    const int smid = warp_scan_bound(row, t0 + 1, s0, lane);
    const int send = warp_scan_bound(row, t0 + 2, smid, lane);

    const int* __restrict__ xr = x + (size_t)b * S_BYTES;
    const uint2* __restrict__ p = reinterpret_cast<const uint2*>(g_proj_h);  // 256/row

    float4* __restrict__ obase =
        reinterpret_cast<float4*>(out) + (((size_t)b * NUM_TOK) + t0) * (EMB_DIM / 4);

    #pragma unroll
    for (int tok = 0; tok < 2; ++tok) {
        const int a = (tok == 0) ? s0 : smid;
        const int z = (tok == 0) ? smid : send;
        const int cnt = z - a;

        __half2 acc[8][2];
        #pragma unroll
        for (int j = 0; j < 8; ++j) {
            acc[j][0] = __float2half2_rn(0.f);
            acc[j][1] = __float2half2_rn(0.f);
        }

        for (int s = a; s < z; ++s) {
            const int e = xr[s];  // warp-broadcast load, L1-hit
            const uint2* __restrict__ pr = p + (size_t)e * (EMB_DIM / 4);
            #pragma unroll
            for (int j = 0; j < 8; ++j) {
                uint2 u = pr[lane + 32 * j];  // coalesced 256B wavefront, L2-hit
                acc[j][0] = __hadd2(acc[j][0], *reinterpret_cast<__half2*>(&u.x));
                acc[j][1] = __hadd2(acc[j][1], *reinterpret_cast<__half2*>(&u.y));
            }
        }

        const float inv = 1.0f / (float)(cnt > 0 ? cnt : 1);
        float4* __restrict__ o = obase + (size_t)tok * (EMB_DIM / 4);
        #pragma unroll
        for (int j = 0; j < 8; ++j) {
            float2 f0 = __half22float2(acc[j][0]);
            float2 f1 = __half22float2(acc[j][1]);
            float4 v = make_float4(f0.x * inv, f0.y * inv, f1.x * inv, f1.y * inv);
            __stcs(&o[lane + 32 * j], v);  // contiguous STG.128.CS
        }
    }
}

// ---------------------------------------------------------------------------
// Launch
// ---------------------------------------------------------------------------
extern "C" void kernel_launch(void* const* d_in, const int* in_sizes, int n_in,
                              void* d_out, int out_size) {
    const int*   x    = (const int*)  d_in[0];  // [B, S_BYTES] int32
    const int*   bg   = (const int*)  d_in[1];  // [B, S_BYTES] int32 (sorted per row)
    const float* emb  = (const float*)d_in[2];  // [NUM_EMB, BYTE_DIM] fp32
    const float* wout = (const float*)d_in[3];  // [EMB_DIM, BYTE_DIM] fp32
    float* out = (float*)d_out;                 // [B, NUM_TOK, EMB_DIM] fp32

    (void)in_sizes; (void)n_in; (void)out_size;

    proj_gemm_kernel<<<(EMB_DIM / BN) * (NUM_EMB / BM), 256>>>(emb, wout);  // 384 blocks

    dim3 pgrid(NUM_TOK / 16, BATCH);            // (128, 8) = 1024 blocks
    pool_kernel<<<pgrid, 256>>>(x, bg, out);
}